// round 17
// baseline (speedup 1.0000x reference)
#include <cuda_runtime.h>
#include <cfloat>

// x: (16, 256, 128, 128) fp32 NCHW.  y = 2 * revcummax_W( revcummax_H( x ) )
//
// One CTA (256 threads) per image, FOUR 32-row phases bottom-to-top.
// Per-column running max carried across phases in double-buffered colmax[].
// Tile 32 x 132 fp32 (16.9 KB), 8 CTAs/SM, 3.5-wave schedule (multi-wave
// absorbs the slowest-SM spread that single-wave designs pay in bench).
// H-scan: 16-row segment per thread in smem. W-scan: registers + shuffles,
// fused with the store. At the measured mixed-stream DRAM ceiling
// (~5.8 TB/s, ncu 82.8us ~= 537MB/6.5TB/s floor); R13 trims dead work:
// first phase skips the colmax init/load/fold (carry == -FLT_MAX),
// last phase skips the carry update + trailing sync.

#define IMG_W 128
#define IMG_H 128
#define PH 32                 // rows per phase
#define NPH 4
#define PITCH 132             // 128 + 4 -> float4-aligned rows, conflict-free

__device__ __forceinline__ float4 f4max(float4 a, float4 b) {
    a.x = fmaxf(a.x, b.x); a.y = fmaxf(a.y, b.y);
    a.z = fmaxf(a.z, b.z); a.w = fmaxf(a.w, b.w);
    return a;
}

__global__ void __launch_bounds__(256, 8)
tlc_kernel(const float* __restrict__ x, float* __restrict__ y) {
    __shared__ float tile[PH * PITCH];     // 16896 B
    __shared__ float colmax[2][IMG_W];     // 1024 B, double-buffered carry

    const int t    = threadIdx.x;
    const int lane = t & 31;
    const int wid  = t >> 5;               // 0..7
    const int col  = t & 127;              // H-scan column
    const int hseg = t >> 7;               // 0 or 1 (16-row segment)
    const long long base = (long long)blockIdx.x * (IMG_H * IMG_W);

    #pragma unroll
    for (int i = 0; i < NPH; ++i) {        // i is compile-time (full unroll)
        const int phase = NPH - 1 - i;     // 3,2,1,0
        const int cur = i & 1, nxt = cur ^ 1;
        const float4* __restrict__ xin4 =
            (const float4*)(x + base + phase * (PH * IMG_W));
        float4* __restrict__ yout4 =
            (float4*)(y + base + phase * (PH * IMG_W));

        // ---- load 32x128: warp owns 4 rows, float4 LDG -> STS.128 ----
        #pragma unroll
        for (int k = 0; k < 4; ++k) {
            int r = wid * 4 + k;
            float4 v = __ldcs(&xin4[r * 32 + lane]);
            *(float4*)&tile[r * PITCH + 4 * lane] = v;
        }
        __syncthreads();

        // ---- H-scan: 16-row segment-local reverse cummax per column ----
        {
            const int r0 = hseg * 16;
            float run = -FLT_MAX;
            #pragma unroll
            for (int j = 15; j >= 0; --j) {
                int idx = (r0 + j) * PITCH + col;
                run = fmaxf(run, tile[idx]);
                tile[idx] = run;
            }
        }
        __syncthreads();

        // ---- W pass fused with store; tile + colmax[cur] READ-ONLY ----
        {
            float4 t16 = *(const float4*)&tile[16 * PITCH + 4 * lane]; // seg1 total
            float4 cm, f0;
            if (i == 0) {
                // no carry yet: fold for rows 0..15 is just the seg-1 total
                cm = make_float4(-FLT_MAX, -FLT_MAX, -FLT_MAX, -FLT_MAX);
                f0 = t16;
            } else {
                cm = *(const float4*)&colmax[cur][4 * lane];
                f0 = f4max(cm, t16);
            }
            #pragma unroll
            for (int k = 0; k < 4; ++k) {
                int r = wid * 4 + k;
                float4 v = *(const float4*)&tile[r * PITCH + 4 * lane];
                if (i == 0) {
                    if (r < 16) v = f4max(v, f0);
                } else {
                    v = f4max(v, (r < 16) ? f0 : cm);
                }

                // in-quad reverse cummax
                v.z = fmaxf(v.z, v.w);
                v.y = fmaxf(v.y, v.z);
                v.x = fmaxf(v.x, v.y);

                // warp suffix-max of quad totals (predicate-free), excl shift
                float s = v.x;
                #pragma unroll
                for (int d = 1; d < 32; d <<= 1)
                    s = fmaxf(s, __shfl_down_sync(0xffffffffu, s, d));
                float e = __shfl_down_sync(0xffffffffu, s, 1);
                if (lane == 31) e = -FLT_MAX;

                float4 o;
                o.x = 2.0f * fmaxf(v.x, e);
                o.y = 2.0f * fmaxf(v.y, e);
                o.z = 2.0f * fmaxf(v.z, e);
                o.w = 2.0f * fmaxf(v.w, e);
                __stcs(&yout4[r * 32 + lane], o);
            }
        }

        // ---- carry update into the OTHER buffer; skip on last phase ----
        if (i < NPH - 1) {
            if (t < IMG_W) {
                float tot = fmaxf(tile[0 * PITCH + t], tile[16 * PITCH + t]);
                colmax[nxt][t] = (i == 0) ? tot
                                          : fmaxf(colmax[cur][t], tot);
            }
            __syncthreads();   // tile/colmax stable before next phase's load
        }
    }
}

extern "C" void kernel_launch(void* const* d_in, const int* in_sizes, int n_in,
                              void* d_out, int out_size) {
    const float* x = (const float*)d_in[0];
    float* y = (float*)d_out;
    const int n_imgs = in_sizes[0] / (IMG_H * IMG_W);   // 4096
    tlc_kernel<<<n_imgs, 256>>>(x, y);
}